// round 1
// baseline (speedup 1.0000x reference)
#include <cuda_runtime.h>
#include <stdint.h>

// Problem constants
#define TT   256
#define BB   128
#define NIN  784
#define NHID 512
#define NOUT 128
#define MM   (TT*BB)        // 32768 (t,b) pairs
#define NBW  25             // 32-bit words covering 784 inputs

// CUBA constants, computed in double then truncated to fp32 exactly as JAX does.
#define C_A ((float)(1e-6*(1.0/6e-6)))            // dt*tau_mem_inv = 0.16666667f
#define C_D ((float)(1.0 - 1e-6*(1.0/6e-6)))     // 1 - dt*tau_syn_inv = 0.8333333f

// ---- scratch (device globals; no allocations allowed) ----
__device__ float    g_wT  [NIN*NHID];        // w_hidden transposed: [i][h]   1.6 MB
__device__ float    g_woT [NHID*NOUT];       // w_out transposed:    [h][o]   256 KB
__device__ uint32_t g_bits[MM*NBW];          // input spike bitmasks          3.3 MB
__device__ float    g_ch  [(size_t)MM*NHID]; // hidden synaptic input         67 MB
__device__ uint32_t g_sbits[MM*(NHID/32)];   // hidden spike bitmasks         2 MB
__device__ float    g_co  [MM*NOUT];         // output synaptic input         16.8 MB

// ---------------- prep kernels ----------------
__global__ void k_transpose_w(const float* __restrict__ w) {
    int idx = blockIdx.x*blockDim.x + threadIdx.x;
    if (idx < NIN*NHID) {
        int i = idx / NHID, h = idx % NHID;
        g_wT[idx] = w[h*NIN + i];
    }
}

__global__ void k_transpose_wo(const float* __restrict__ w) {
    int idx = blockIdx.x*blockDim.x + threadIdx.x;
    if (idx < NHID*NOUT) {
        int h = idx / NOUT, o = idx % NOUT;
        g_woT[idx] = w[o*NHID + h];
    }
}

// One block per (t,b) pair; 800 threads = 25 warps cover 784 inputs (tail zero).
__global__ void k_pack(const float* __restrict__ spikes) {
    int m   = blockIdx.x;
    int tid = threadIdx.x;
    float v = (tid < NIN) ? spikes[(size_t)m*NIN + tid] : 0.0f;
    uint32_t msk = __ballot_sync(0xffffffffu, v != 0.0f);
    if ((tid & 31) == 0) g_bits[m*NBW + (tid >> 5)] = msk;
}

// ---------------- GEMM1: c_h[m,h] = sum_{active i} wT[i,h] ----------------
// Warp per pair, grid.y = 8 chunks of 64 h-columns (196KB wT chunk -> L1 resident).
__global__ void k_gemm1() {
    int lane = threadIdx.x & 31;
    int m    = blockIdx.x*8 + (threadIdx.x >> 5);
    int c    = blockIdx.y;                       // 0..7
    const float*    wbase = g_wT + c*64 + lane*2;
    const uint32_t* bp    = g_bits + m*NBW;
    float ax = 0.0f, ay = 0.0f;
    #pragma unroll 1
    for (int k = 0; k < NBW; k++) {
        uint32_t msk = bp[k];
        while (msk) {
            int b = __ffs(msk) - 1;
            msk &= msk - 1;
            float2 w = *(const float2*)(wbase + (k*32 + b)*NHID);
            ax += w.x; ay += w.y;
        }
    }
    float2 r; r.x = ax; r.y = ay;
    *(float2*)(g_ch + (size_t)m*NHID + c*64 + lane*2) = r;
}

// ---------------- LIF scan (sequential in t, parallel over b*h) ----------------
__global__ void k_lif() {
    int gid  = blockIdx.x*blockDim.x + threadIdx.x;   // b*512 + h, 65536 threads
    int lane = threadIdx.x & 31;
    int sb   = gid >> 5;                              // b*16 + word
    float v = 0.0f, cur = 0.0f;
    #pragma unroll 1
    for (int t = 0; t < TT; t++) {
        float x = g_ch[(size_t)t*(BB*NHID) + gid];
        v   = v + C_A*(cur - v);     // membrane update with OLD current
        cur = cur*C_D + x;           // synaptic decay + input
        bool z = v > 1.0f;           // threshold (V_TH = 1)
        uint32_t msk = __ballot_sync(0xffffffffu, z);
        if (z) v = 0.0f;             // reset
        if (lane == 0) g_sbits[t*2048 + sb] = msk;
    }
}

// ---------------- GEMM2: c_o[m,o] = sum_{active h} woT[h,o] ----------------
// Warp per pair, grid.y = 2 chunks of 64 o-columns (128KB woT chunk -> L1 resident).
__global__ void k_gemm2() {
    int lane = threadIdx.x & 31;
    int m    = blockIdx.x*8 + (threadIdx.x >> 5);
    int c    = blockIdx.y;                       // 0..1
    const float*    wbase = g_woT + c*64 + lane*2;
    const uint32_t* bp    = g_sbits + m*16;
    float ax = 0.0f, ay = 0.0f;
    #pragma unroll 1
    for (int k = 0; k < 16; k++) {
        uint32_t msk = bp[k];
        while (msk) {
            int b = __ffs(msk) - 1;
            msk &= msk - 1;
            float2 w = *(const float2*)(wbase + (k*32 + b)*NOUT);
            ax += w.x; ay += w.y;
        }
    }
    float2 r; r.x = ax; r.y = ay;
    *(float2*)(g_co + m*NOUT + c*64 + lane*2) = r;
}

// ---------------- LI scan (readout membrane trace) ----------------
__global__ void k_li(float* __restrict__ out) {
    int gid = blockIdx.x*blockDim.x + threadIdx.x;    // b*128 + o, 16384 threads
    float v = 0.0f, cur = 0.0f;
    #pragma unroll 1
    for (int t = 0; t < TT; t++) {
        float x = g_co[t*(BB*NOUT) + gid];
        v   = v + C_A*(cur - v);
        cur = cur*C_D + x;
        out[t*(BB*NOUT) + gid] = v;
    }
}

// ---------------- launch ----------------
extern "C" void kernel_launch(void* const* d_in, const int* in_sizes, int n_in,
                              void* d_out, int out_size) {
    const float *spikes = nullptr, *wh = nullptr, *wo = nullptr;
    for (int i = 0; i < n_in; i++) {
        if      (in_sizes[i] == TT*BB*NIN) spikes = (const float*)d_in[i];
        else if (in_sizes[i] == NHID*NIN)  wh     = (const float*)d_in[i];
        else if (in_sizes[i] == NOUT*NHID) wo     = (const float*)d_in[i];
    }
    k_transpose_w <<<(NIN*NHID  + 255)/256, 256>>>(wh);
    k_transpose_wo<<<(NHID*NOUT + 255)/256, 256>>>(wo);
    k_pack        <<<MM, 800>>>(spikes);
    k_gemm1       <<<dim3(MM/8, 8), 256>>>();
    k_lif         <<<(BB*NHID)/256, 256>>>();
    k_gemm2       <<<dim3(MM/8, 2), 256>>>();
    k_li          <<<(BB*NOUT)/256, 256>>>((float*)d_out);
}

// round 2
// speedup vs baseline: 1.6705x; 1.6705x over previous
#include <cuda_runtime.h>
#include <stdint.h>

// Problem constants
#define TT   256
#define BB   128
#define NIN  784
#define NHID 512
#define NOUT 128
#define MM   (TT*BB)        // 32768 (t,b) pairs
#define LIST1_PAD 800       // per-pair input index list capacity (mult of 8)

// CUBA constants (exactly fp32-rounded like JAX)
#define C_A ((float)(1e-6*(1.0/6e-6)))           // 0.16666667f
#define C_D ((float)(1.0 - 1e-6*(1.0/6e-6)))     // 0.8333333f

// ---- scratch (device globals; no allocations allowed) ----
__device__ float    g_wT  [NIN*NHID];          // w_hidden^T [i][h]      1.6 MB
__device__ float    g_woT [NHID*NOUT];         // w_out^T    [h][o]      256 KB
__device__ uint16_t g_idx [MM*LIST1_PAD];      // input active lists     52 MB
__device__ int      g_cnt [MM];
__device__ float    g_ch  [(size_t)MM*NHID];   // hidden synaptic input  67 MB
__device__ uint32_t g_sbits[MM*(NHID/32)];     // hidden spike bitmasks  2 MB
__device__ uint16_t g_hidx[MM*NHID];           // hidden active lists    33.5 MB
__device__ int      g_hcnt[MM];
__device__ float    g_co  [MM*NOUT];           // output synaptic input  16.8 MB

// ---------------- prep ----------------
__global__ void k_transpose_w(const float* __restrict__ w) {
    int idx = blockIdx.x*blockDim.x + threadIdx.x;
    if (idx < NIN*NHID) {
        int i = idx / NHID, h = idx % NHID;
        g_wT[idx] = w[h*NIN + i];
    }
}
__global__ void k_transpose_wo(const float* __restrict__ w) {
    int idx = blockIdx.x*blockDim.x + threadIdx.x;
    if (idx < NHID*NOUT) {
        int h = idx / NOUT, o = idx % NOUT;
        g_woT[idx] = w[o*NHID + h];
    }
}

// Pack + compact: one block per (t,b) pair. Produces ascending uint16 index lists.
__global__ void k_pack(const float* __restrict__ spikes) {
    __shared__ int s_cnt[25];
    int m   = blockIdx.x;
    int tid = threadIdx.x;          // 0..799
    int w   = tid >> 5, lane = tid & 31;
    float v = (tid < NIN) ? spikes[(size_t)m*NIN + tid] : 0.0f;
    uint32_t msk = __ballot_sync(0xffffffffu, v != 0.0f);
    if (lane == 0) s_cnt[w] = __popc(msk);
    __syncthreads();
    if (tid == 0) {
        int run = 0;
        #pragma unroll
        for (int q = 0; q < 25; q++) { int t = s_cnt[q]; s_cnt[q] = run; run += t; }
        g_cnt[m] = run;
    }
    __syncthreads();
    if (v != 0.0f) {
        int pos = s_cnt[w] + __popc(msk & ((1u << lane) - 1u));
        g_idx[m*LIST1_PAD + pos] = (uint16_t)tid;
    }
}

// ---------------- GEMM1: c_h[m,h] = sum_{active i} wT[i,h] ----------------
// Warp per (pair, 64-col chunk). 8 chunks of 64 h-cols -> 196KB wT slab, L1-resident.
__global__ void k_gemm1() {
    int lane = threadIdx.x & 31;
    int m    = blockIdx.x*8 + (threadIdx.x >> 5);
    int c    = blockIdx.y;                       // 0..7
    const float*    wbase = g_wT + c*64 + lane*2;
    const uint16_t* lst   = g_idx + m*LIST1_PAD;
    int cnt = g_cnt[m];
    float ax = 0.0f, ay = 0.0f;
    int j = 0;
    #pragma unroll 1
    for (; j + 8 <= cnt; j += 8) {
        uint4 p = *(const uint4*)(lst + j);      // 8 uint16 indices, broadcast load
        int i0 =  p.x & 0xffff, i1 = p.x >> 16;
        int i2 =  p.y & 0xffff, i3 = p.y >> 16;
        int i4 =  p.z & 0xffff, i5 = p.z >> 16;
        int i6 =  p.w & 0xffff, i7 = p.w >> 16;
        float2 w0 = *(const float2*)(wbase + i0*NHID);
        float2 w1 = *(const float2*)(wbase + i1*NHID);
        float2 w2 = *(const float2*)(wbase + i2*NHID);
        float2 w3 = *(const float2*)(wbase + i3*NHID);
        float2 w4 = *(const float2*)(wbase + i4*NHID);
        float2 w5 = *(const float2*)(wbase + i5*NHID);
        float2 w6 = *(const float2*)(wbase + i6*NHID);
        float2 w7 = *(const float2*)(wbase + i7*NHID);
        ax += w0.x; ay += w0.y;  ax += w1.x; ay += w1.y;
        ax += w2.x; ay += w2.y;  ax += w3.x; ay += w3.y;
        ax += w4.x; ay += w4.y;  ax += w5.x; ay += w5.y;
        ax += w6.x; ay += w6.y;  ax += w7.x; ay += w7.y;
    }
    #pragma unroll 1
    for (; j < cnt; j++) {
        float2 w = *(const float2*)(wbase + ((int)lst[j])*NHID);
        ax += w.x; ay += w.y;
    }
    float2 r; r.x = ax; r.y = ay;
    *(float2*)(g_ch + (size_t)m*NHID + c*64 + lane*2) = r;
}

// ---------------- LIF scan with software prefetch (depth 8) ----------------
__global__ void k_lif() {
    int gid  = blockIdx.x*blockDim.x + threadIdx.x;   // b*512 + h
    int lane = threadIdx.x & 31;
    int sb   = gid >> 5;
    float v = 0.0f, cur = 0.0f;
    float xs[8];
    #pragma unroll
    for (int p = 0; p < 8; p++) xs[p] = g_ch[(size_t)p*(BB*NHID) + gid];
    #pragma unroll 1
    for (int t0 = 0; t0 < TT; t0 += 8) {
        #pragma unroll
        for (int p = 0; p < 8; p++) {
            float x = xs[p];
            int tn = t0 + 8 + p;
            if (tn < TT) xs[p] = g_ch[(size_t)tn*(BB*NHID) + gid];
            v   = v + C_A*(cur - v);
            cur = cur*C_D + x;
            bool z = v > 1.0f;
            uint32_t msk = __ballot_sync(0xffffffffu, z);
            if (z) v = 0.0f;
            if (lane == 0) g_sbits[(t0 + p)*2048 + sb] = msk;
        }
    }
}

// ---------------- hidden spike list compaction: one warp per pair ----------------
__global__ void k_hidlist() {
    int m    = blockIdx.x*8 + (threadIdx.x >> 5);
    int lane = threadIdx.x & 31;
    uint32_t w = (lane < 16) ? g_sbits[m*16 + lane] : 0u;
    int cnt = __popc(w);
    // inclusive warp scan of counts
    int sc = cnt;
    #pragma unroll
    for (int d = 1; d < 32; d <<= 1) {
        int o = __shfl_up_sync(0xffffffffu, sc, d);
        if (lane >= d) sc += o;
    }
    int base = sc - cnt;                  // exclusive prefix
    if (lane == 31) g_hcnt[m] = sc;
    uint16_t* out = g_hidx + m*NHID;
    int hb = lane*32;
    while (w) {
        int b = __ffs(w) - 1;
        w &= w - 1;
        out[base++] = (uint16_t)(hb + b);
    }
}

// ---------------- GEMM2: c_o[m,o] = sum_{active h} woT[h,o] ----------------
__global__ void k_gemm2() {
    int lane = threadIdx.x & 31;
    int m    = blockIdx.x*8 + (threadIdx.x >> 5);
    int c    = blockIdx.y;                       // 0..1
    const float*    wbase = g_woT + c*64 + lane*2;
    const uint16_t* lst   = g_hidx + m*NHID;
    int cnt = g_hcnt[m];
    float ax = 0.0f, ay = 0.0f;
    int j = 0;
    #pragma unroll 1
    for (; j + 8 <= cnt; j += 8) {
        uint4 p = *(const uint4*)(lst + j);
        int i0 =  p.x & 0xffff, i1 = p.x >> 16;
        int i2 =  p.y & 0xffff, i3 = p.y >> 16;
        int i4 =  p.z & 0xffff, i5 = p.z >> 16;
        int i6 =  p.w & 0xffff, i7 = p.w >> 16;
        float2 w0 = *(const float2*)(wbase + i0*NOUT);
        float2 w1 = *(const float2*)(wbase + i1*NOUT);
        float2 w2 = *(const float2*)(wbase + i2*NOUT);
        float2 w3 = *(const float2*)(wbase + i3*NOUT);
        float2 w4 = *(const float2*)(wbase + i4*NOUT);
        float2 w5 = *(const float2*)(wbase + i5*NOUT);
        float2 w6 = *(const float2*)(wbase + i6*NOUT);
        float2 w7 = *(const float2*)(wbase + i7*NOUT);
        ax += w0.x; ay += w0.y;  ax += w1.x; ay += w1.y;
        ax += w2.x; ay += w2.y;  ax += w3.x; ay += w3.y;
        ax += w4.x; ay += w4.y;  ax += w5.x; ay += w5.y;
        ax += w6.x; ay += w6.y;  ax += w7.x; ay += w7.y;
    }
    #pragma unroll 1
    for (; j < cnt; j++) {
        float2 w = *(const float2*)(wbase + ((int)lst[j])*NOUT);
        ax += w.x; ay += w.y;
    }
    float2 r; r.x = ax; r.y = ay;
    *(float2*)(g_co + m*NOUT + c*64 + lane*2) = r;
}

// ---------------- LI scan with software prefetch ----------------
__global__ void k_li(float* __restrict__ out) {
    int gid = blockIdx.x*blockDim.x + threadIdx.x;    // b*128 + o
    float v = 0.0f, cur = 0.0f;
    float xs[8];
    #pragma unroll
    for (int p = 0; p < 8; p++) xs[p] = g_co[p*(BB*NOUT) + gid];
    #pragma unroll 1
    for (int t0 = 0; t0 < TT; t0 += 8) {
        #pragma unroll
        for (int p = 0; p < 8; p++) {
            float x = xs[p];
            int tn = t0 + 8 + p;
            if (tn < TT) xs[p] = g_co[tn*(BB*NOUT) + gid];
            v   = v + C_A*(cur - v);
            cur = cur*C_D + x;
            out[(t0 + p)*(BB*NOUT) + gid] = v;
        }
    }
}

// ---------------- launch ----------------
extern "C" void kernel_launch(void* const* d_in, const int* in_sizes, int n_in,
                              void* d_out, int out_size) {
    const float *spikes = nullptr, *wh = nullptr, *wo = nullptr;
    for (int i = 0; i < n_in; i++) {
        if      (in_sizes[i] == TT*BB*NIN) spikes = (const float*)d_in[i];
        else if (in_sizes[i] == NHID*NIN)  wh     = (const float*)d_in[i];
        else if (in_sizes[i] == NOUT*NHID) wo     = (const float*)d_in[i];
    }
    k_transpose_w <<<(NIN*NHID  + 255)/256, 256>>>(wh);
    k_transpose_wo<<<(NHID*NOUT + 255)/256, 256>>>(wo);
    k_pack        <<<MM, 800>>>(spikes);
    k_gemm1       <<<dim3(MM/8, 8), 256>>>();
    k_lif         <<<(BB*NHID)/256, 256>>>();
    k_hidlist     <<<MM/8, 256>>>();
    k_gemm2       <<<dim3(MM/8, 2), 256>>>();
    k_li          <<<(BB*NOUT)/256, 256>>>((float*)d_out);
}

// round 5
// speedup vs baseline: 2.3465x; 1.4047x over previous
#include <cuda_runtime.h>
#include <cuda_fp16.h>
#include <stdint.h>

// Problem constants
#define TT   256
#define BB   128
#define NIN  784
#define NHID 512
#define NOUT 128
#define MM   (TT*BB)        // 32768 (t,b) pairs
#define KPAD 832            // 784 padded to 13*64
#define NCH  13             // K chunks of 64
#define MTILES (MM/128)     // 256

// CUBA constants (exactly fp32-rounded like JAX)
#define C_A ((float)(1e-6*(1.0/6e-6)))           // 0.16666667f
#define C_D ((float)(1.0 - 1e-6*(1.0/6e-6)))     // 0.8333333f

// ---- scratch (device globals; no allocations allowed) ----
__device__ __half   g_a16 [(size_t)MM*KPAD];   // spikes fp16 K-padded    54.5 MB
__device__ __half   g_bhi [NHID*KPAD];         // w_hidden hi fp16        0.85 MB
__device__ __half   g_blo [NHID*KPAD];         // w_hidden lo fp16        0.85 MB
__device__ float    g_woT [NHID*NOUT];         // w_out^T [h][o]          256 KB
__device__ float    g_ch  [(size_t)MM*NHID];   // hidden synaptic input   67 MB
__device__ uint32_t g_sbits[MM*(NHID/32)];     // hidden spike bitmasks   2 MB
__device__ uint16_t g_hidx[MM*NHID];           // hidden active lists     33.5 MB
__device__ int      g_hcnt[MM];
__device__ float    g_co  [MM*NOUT];           // output synaptic input   16.8 MB

// ================= PTX helpers =================
__device__ __forceinline__ uint32_t smem_u32(const void* p) {
    uint32_t a;
    asm("{ .reg .u64 t; cvta.to.shared.u64 t, %1; cvt.u32.u64 %0, t; }" : "=r"(a) : "l"(p));
    return a;
}
#define CP_ASYNC16(dst, src) \
    asm volatile("cp.async.cg.shared.global [%0], [%1], 16;" :: "r"(dst), "l"(src))
#define CP_COMMIT()  asm volatile("cp.async.commit_group;" ::: "memory")
#define CP_WAIT(n)   asm volatile("cp.async.wait_group %0;" :: "n"(n) : "memory")

#define LDSM_X4(r0,r1,r2,r3, a) \
    asm volatile("ldmatrix.sync.aligned.m8n8.x4.shared.b16 {%0,%1,%2,%3}, [%4];" \
        : "=r"(r0),"=r"(r1),"=r"(r2),"=r"(r3) : "r"(a))
#define MMA16816(d, a0,a1,a2,a3, b0,b1) \
    asm volatile("mma.sync.aligned.m16n8k16.row.col.f32.f16.f16.f32 " \
        "{%0,%1,%2,%3}, {%4,%5,%6,%7}, {%8,%9}, {%0,%1,%2,%3};" \
        : "+f"((d)[0]),"+f"((d)[1]),"+f"((d)[2]),"+f"((d)[3]) \
        : "r"(a0),"r"(a1),"r"(a2),"r"(a3),"r"(b0),"r"(b1))

#define SWZ(off) ((off) ^ (((off) >> 3) & 0x70))

// ================= conversion kernels =================
// spikes fp32 [MM][784] -> fp16 [MM][832] (pad zero)
__global__ void k_a16(const float* __restrict__ spikes) {
    int m = blockIdx.x;
    int c = threadIdx.x * 2;                 // 0..830
    __half2 h;
    if (c + 1 < NIN) {
        float2 v = *(const float2*)(spikes + (size_t)m*NIN + c);
        h = __floats2half2_rn(v.x, v.y);
    } else {
        h = __floats2half2_rn(0.f, 0.f);
    }
    *(__half2*)(g_a16 + (size_t)m*KPAD + c) = h;
}

// w_hidden [512][784] fp32 -> hi/lo fp16 [512][832]
__global__ void k_bsplit(const float* __restrict__ w) {
    int idx = blockIdx.x*blockDim.x + threadIdx.x;
    if (idx >= NHID*KPAD) return;
    int h = idx / KPAD, k = idx % KPAD;
    __half hi = __float2half_rn(0.f), lo = __float2half_rn(0.f);
    if (k < NIN) {
        float wv = w[h*NIN + k];
        hi = __float2half_rn(wv);
        lo = __float2half_rn(wv - __half2float(hi));
    }
    g_bhi[idx] = hi;
    g_blo[idx] = lo;
}

__global__ void k_transpose_wo(const float* __restrict__ w) {
    int idx = blockIdx.x*blockDim.x + threadIdx.x;
    if (idx < NHID*NOUT) {
        int h = idx / NOUT, o = idx % NOUT;
        g_woT[idx] = w[o*NHID + h];
    }
}

// ================= GEMM1: mma.sync fp16 2-way split =================
// C[128x128 per CTA] = A[128xK] (spikes) x (Bhi + Blo)[128xK]^T, fp32 accum.
// SMEM stage: A 16KB + Bhi 16KB + Blo 16KB = 48KB; 2 stages = 96KB.
#define STAGE_BYTES 49152

__global__ void __launch_bounds__(256, 2) k_gemm1tc() {
    extern __shared__ char smem[];
    const int tid    = threadIdx.x;
    const int wid    = tid >> 5;
    const int lane   = tid & 31;
    const int warp_m = wid >> 1;            // 0..3  (32 rows)
    const int warp_n = wid &  1;            // 0..1  (64 cols)
    const int m_base = blockIdx.x * 128;
    const int n_base = blockIdx.y * 128;

    const uint32_t sbase = smem_u32(smem);

    // cp.async loader for chunk kc into stage s
    auto load_tile = [&](int kc, int s) {
        const uint32_t st = sbase + s * STAGE_BYTES;
        const int kcol = kc * 64;
        #pragma unroll
        for (int it = 0; it < 4; it++) {
            int g = it * 256 + tid;              // A granules: 1024
            int row = g >> 3, sub = g & 7;
            uint32_t off = row * 128 + sub * 16;
            const char* src = (const char*)(g_a16 + (size_t)(m_base + row)*KPAD + kcol) + sub*16;
            CP_ASYNC16(st + SWZ(off), src);
        }
        #pragma unroll
        for (int it = 0; it < 4; it++) {
            int g = it * 256 + tid;
            int row = g >> 3, sub = g & 7;
            uint32_t off = row * 128 + sub * 16;
            const char* srch = (const char*)(g_bhi + (size_t)(n_base + row)*KPAD + kcol) + sub*16;
            const char* srcl = (const char*)(g_blo + (size_t)(n_base + row)*KPAD + kcol) + sub*16;
            CP_ASYNC16(st + 16384 + SWZ(off), srch);
            CP_ASYNC16(st + 32768 + SWZ(off), srcl);
        }
        CP_COMMIT();
    };

    float acc[2][8][4];
    #pragma unroll
    for (int i = 0; i < 2; i++)
        #pragma unroll
        for (int j = 0; j < 8; j++)
            #pragma unroll
            for (int q = 0; q < 4; q++) acc[i][j][q] = 0.f;

    load_tile(0, 0);

    const int lrow = lane & 15, lcol = (lane >> 4) * 16;

    #pragma unroll 1
    for (int c = 0; c < NCH; c++) {
        const int buf = c & 1;
        if (c + 1 < NCH) { load_tile(c + 1, buf ^ 1); CP_WAIT(1); }
        else            { CP_WAIT(0); }
        __syncthreads();

        const uint32_t sA = sbase + buf * STAGE_BYTES;
        const uint32_t sBh = sA + 16384;
        const uint32_t sBl = sA + 32768;

        #pragma unroll
        for (int ks = 0; ks < 4; ks++) {
            uint32_t a[2][4], bh[4][4], bl[4][4];
            #pragma unroll
            for (int mt = 0; mt < 2; mt++) {
                uint32_t off = (uint32_t)(warp_m*32 + mt*16 + lrow)*128 + ks*32 + lcol;
                LDSM_X4(a[mt][0], a[mt][1], a[mt][2], a[mt][3], sA + SWZ(off));
            }
            #pragma unroll
            for (int nt = 0; nt < 4; nt++) {
                uint32_t off = (uint32_t)(warp_n*64 + nt*16 + lrow)*128 + ks*32 + lcol;
                uint32_t so = SWZ(off);
                // NON-trans: smem tile is [n][k] K-major, which IS the mma "col" B fragment layout
                LDSM_X4(bh[nt][0], bh[nt][1], bh[nt][2], bh[nt][3], sBh + so);
                LDSM_X4(bl[nt][0], bl[nt][1], bl[nt][2], bl[nt][3], sBl + so);
            }
            #pragma unroll
            for (int mt = 0; mt < 2; mt++)
                #pragma unroll
                for (int nt = 0; nt < 4; nt++) {
                    MMA16816(acc[mt][nt*2+0], a[mt][0],a[mt][1],a[mt][2],a[mt][3],
                             bh[nt][0], bh[nt][2]);
                    MMA16816(acc[mt][nt*2+1], a[mt][0],a[mt][1],a[mt][2],a[mt][3],
                             bh[nt][1], bh[nt][3]);
                    MMA16816(acc[mt][nt*2+0], a[mt][0],a[mt][1],a[mt][2],a[mt][3],
                             bl[nt][0], bl[nt][2]);
                    MMA16816(acc[mt][nt*2+1], a[mt][0],a[mt][1],a[mt][2],a[mt][3],
                             bl[nt][1], bl[nt][3]);
                }
        }
        __syncthreads();
    }

    // epilogue: m16n8 D fragment: rows (lane>>2, +8), cols (lane&3)*2 + {0,1}
    const int erow = lane >> 2, ecol = (lane & 3) * 2;
    #pragma unroll
    for (int mt = 0; mt < 2; mt++) {
        #pragma unroll
        for (int nt = 0; nt < 8; nt++) {
            int col = n_base + warp_n*64 + nt*8 + ecol;
            int r0  = m_base + warp_m*32 + mt*16 + erow;
            float2 v0; v0.x = acc[mt][nt][0]; v0.y = acc[mt][nt][1];
            float2 v1; v1.x = acc[mt][nt][2]; v1.y = acc[mt][nt][3];
            *(float2*)(g_ch + (size_t)r0*NHID + col)       = v0;
            *(float2*)(g_ch + (size_t)(r0 + 8)*NHID + col) = v1;
        }
    }
}

// ================= LIF scan with software prefetch (depth 8) =================
__global__ void k_lif() {
    int gid  = blockIdx.x*blockDim.x + threadIdx.x;   // b*512 + h
    int lane = threadIdx.x & 31;
    int sb   = gid >> 5;
    float v = 0.0f, cur = 0.0f;
    float xs[8];
    #pragma unroll
    for (int p = 0; p < 8; p++) xs[p] = g_ch[(size_t)p*(BB*NHID) + gid];
    #pragma unroll 1
    for (int t0 = 0; t0 < TT; t0 += 8) {
        #pragma unroll
        for (int p = 0; p < 8; p++) {
            float x = xs[p];
            int tn = t0 + 8 + p;
            if (tn < TT) xs[p] = g_ch[(size_t)tn*(BB*NHID) + gid];
            v   = v + C_A*(cur - v);
            cur = cur*C_D + x;
            bool z = v > 1.0f;
            uint32_t msk = __ballot_sync(0xffffffffu, z);
            if (z) v = 0.0f;
            if (lane == 0) g_sbits[(t0 + p)*2048 + sb] = msk;
        }
    }
}

// ================= hidden spike list compaction: one warp per pair =================
__global__ void k_hidlist() {
    int m    = blockIdx.x*8 + (threadIdx.x >> 5);
    int lane = threadIdx.x & 31;
    uint32_t w = (lane < 16) ? g_sbits[m*16 + lane] : 0u;
    int cnt = __popc(w);
    int sc = cnt;
    #pragma unroll
    for (int d = 1; d < 32; d <<= 1) {
        int o = __shfl_up_sync(0xffffffffu, sc, d);
        if (lane >= d) sc += o;
    }
    int base = sc - cnt;
    if (lane == 31) g_hcnt[m] = sc;
    uint16_t* out = g_hidx + m*NHID;
    int hb = lane*32;
    while (w) {
        int b = __ffs(w) - 1;
        w &= w - 1;
        out[base++] = (uint16_t)(hb + b);
    }
}

// ================= GEMM2: c_o[m,o] = sum_{active h} woT[h,o] =================
__global__ void k_gemm2() {
    int lane = threadIdx.x & 31;
    int m    = blockIdx.x*8 + (threadIdx.x >> 5);
    int c    = blockIdx.y;
    const float*    wbase = g_woT + c*64 + lane*2;
    const uint16_t* lst   = g_hidx + m*NHID;
    int cnt = g_hcnt[m];
    float ax = 0.0f, ay = 0.0f;
    int j = 0;
    #pragma unroll 1
    for (; j + 8 <= cnt; j += 8) {
        uint4 p = *(const uint4*)(lst + j);
        int i0 =  p.x & 0xffff, i1 = p.x >> 16;
        int i2 =  p.y & 0xffff, i3 = p.y >> 16;
        int i4 =  p.z & 0xffff, i5 = p.z >> 16;
        int i6 =  p.w & 0xffff, i7 = p.w >> 16;
        float2 w0 = *(const float2*)(wbase + i0*NOUT);
        float2 w1 = *(const float2*)(wbase + i1*NOUT);
        float2 w2 = *(const float2*)(wbase + i2*NOUT);
        float2 w3 = *(const float2*)(wbase + i3*NOUT);
        float2 w4 = *(const float2*)(wbase + i4*NOUT);
        float2 w5 = *(const float2*)(wbase + i5*NOUT);
        float2 w6 = *(const float2*)(wbase + i6*NOUT);
        float2 w7 = *(const float2*)(wbase + i7*NOUT);
        ax += w0.x; ay += w0.y;  ax += w1.x; ay += w1.y;
        ax += w2.x; ay += w2.y;  ax += w3.x; ay += w3.y;
        ax += w4.x; ay += w4.y;  ax += w5.x; ay += w5.y;
        ax += w6.x; ay += w6.y;  ax += w7.x; ay += w7.y;
    }
    #pragma unroll 1
    for (; j < cnt; j++) {
        float2 w = *(const float2*)(wbase + ((int)lst[j])*NOUT);
        ax += w.x; ay += w.y;
    }
    float2 r; r.x = ax; r.y = ay;
    *(float2*)(g_co + m*NOUT + c*64 + lane*2) = r;
}

// ================= LI scan with software prefetch =================
__global__ void k_li(float* __restrict__ out) {
    int gid = blockIdx.x*blockDim.x + threadIdx.x;
    float v = 0.0f, cur = 0.0f;
    float xs[8];
    #pragma unroll
    for (int p = 0; p < 8; p++) xs[p] = g_co[p*(BB*NOUT) + gid];
    #pragma unroll 1
    for (int t0 = 0; t0 < TT; t0 += 8) {
        #pragma unroll
        for (int p = 0; p < 8; p++) {
            float x = xs[p];
            int tn = t0 + 8 + p;
            if (tn < TT) xs[p] = g_co[tn*(BB*NOUT) + gid];
            v   = v + C_A*(cur - v);
            cur = cur*C_D + x;
            out[(t0 + p)*(BB*NOUT) + gid] = v;
        }
    }
}

// ================= launch =================
extern "C" void kernel_launch(void* const* d_in, const int* in_sizes, int n_in,
                              void* d_out, int out_size) {
    const float *spikes = nullptr, *wh = nullptr, *wo = nullptr;
    for (int i = 0; i < n_in; i++) {
        if      (in_sizes[i] == TT*BB*NIN) spikes = (const float*)d_in[i];
        else if (in_sizes[i] == NHID*NIN)  wh     = (const float*)d_in[i];
        else if (in_sizes[i] == NOUT*NHID) wo     = (const float*)d_in[i];
    }
    cudaFuncSetAttribute(k_gemm1tc, cudaFuncAttributeMaxDynamicSharedMemorySize,
                         2*STAGE_BYTES);
    k_bsplit      <<<(NHID*KPAD + 255)/256, 256>>>(wh);
    k_transpose_wo<<<(NHID*NOUT + 255)/256, 256>>>(wo);
    k_a16         <<<MM, KPAD/2>>>(spikes);
    k_gemm1tc     <<<dim3(MTILES, NHID/128), 256, 2*STAGE_BYTES>>>();
    k_lif         <<<(BB*NHID)/256, 256>>>();
    k_hidlist     <<<MM/8, 256>>>();
    k_gemm2       <<<dim3(MM/8, 2), 256>>>();
    k_li          <<<(BB*NOUT)/256, 256>>>((float*)d_out);
}

// round 6
// speedup vs baseline: 2.7153x; 1.1572x over previous
#include <cuda_runtime.h>
#include <cuda_fp16.h>
#include <stdint.h>

// Problem constants
#define TT   256
#define BB   128
#define NIN  784
#define NHID 512
#define NOUT 128
#define MM   (TT*BB)        // 32768 (t,b) pairs
#define KPAD 832            // 784 padded to 13*64
#define NCH  13             // gemm1 K chunks of 64
#define NCH2 8              // gemm2 K chunks of 64 (512/64)
#define MTILES (MM/128)     // 256

// CUBA constants (exactly fp32-rounded like JAX)
#define C_A ((float)(1e-6*(1.0/6e-6)))           // 0.16666667f
#define C_D ((float)(1.0 - 1e-6*(1.0/6e-6)))     // 0.8333333f

// ---- scratch (device globals; no allocations allowed) ----
__device__ __half   g_a16 [(size_t)MM*KPAD];   // spikes fp16 K-padded    54.5 MB
__device__ __half   g_bhi [NHID*KPAD];         // w_hidden hi fp16        0.85 MB
__device__ __half   g_blo [NHID*KPAD];         // w_hidden lo fp16        0.85 MB
__device__ __half   g_ohi [NOUT*NHID];         // w_out hi fp16           128 KB
__device__ __half   g_olo [NOUT*NHID];         // w_out lo fp16           128 KB
__device__ float    g_ch  [(size_t)MM*NHID];   // hidden synaptic input   67 MB
__device__ __half   g_sh  [(size_t)MM*NHID];   // hidden spikes fp16      33.5 MB
__device__ float    g_co  [MM*NOUT];           // output synaptic input   16.8 MB

// ================= PTX helpers =================
__device__ __forceinline__ uint32_t smem_u32(const void* p) {
    uint32_t a;
    asm("{ .reg .u64 t; cvta.to.shared.u64 t, %1; cvt.u32.u64 %0, t; }" : "=r"(a) : "l"(p));
    return a;
}
#define CP_ASYNC16(dst, src) \
    asm volatile("cp.async.cg.shared.global [%0], [%1], 16;" :: "r"(dst), "l"(src))
#define CP_COMMIT()  asm volatile("cp.async.commit_group;" ::: "memory")
#define CP_WAIT(n)   asm volatile("cp.async.wait_group %0;" :: "n"(n) : "memory")

#define LDSM_X4(r0,r1,r2,r3, a) \
    asm volatile("ldmatrix.sync.aligned.m8n8.x4.shared.b16 {%0,%1,%2,%3}, [%4];" \
        : "=r"(r0),"=r"(r1),"=r"(r2),"=r"(r3) : "r"(a))
#define MMA16816(d, a0,a1,a2,a3, b0,b1) \
    asm volatile("mma.sync.aligned.m16n8k16.row.col.f32.f16.f16.f32 " \
        "{%0,%1,%2,%3}, {%4,%5,%6,%7}, {%8,%9}, {%0,%1,%2,%3};" \
        : "+f"((d)[0]),"+f"((d)[1]),"+f"((d)[2]),"+f"((d)[3]) \
        : "r"(a0),"r"(a1),"r"(a2),"r"(a3),"r"(b0),"r"(b1))

#define SWZ(off) ((off) ^ (((off) >> 3) & 0x70))

// ================= conversion kernels =================
// spikes fp32 [MM][784] -> fp16 [MM][832] (pad zero)
__global__ void k_a16(const float* __restrict__ spikes) {
    int m = blockIdx.x;
    int c = threadIdx.x * 2;                 // 0..830
    __half2 h;
    if (c + 1 < NIN) {
        float2 v = *(const float2*)(spikes + (size_t)m*NIN + c);
        h = __floats2half2_rn(v.x, v.y);
    } else {
        h = __floats2half2_rn(0.f, 0.f);
    }
    *(__half2*)(g_a16 + (size_t)m*KPAD + c) = h;
}

// w_hidden [512][784] fp32 -> hi/lo fp16 [512][832]
__global__ void k_bsplit(const float* __restrict__ w) {
    int idx = blockIdx.x*blockDim.x + threadIdx.x;
    if (idx >= NHID*KPAD) return;
    int h = idx / KPAD, k = idx % KPAD;
    __half hi = __float2half_rn(0.f), lo = __float2half_rn(0.f);
    if (k < NIN) {
        float wv = w[h*NIN + k];
        hi = __float2half_rn(wv);
        lo = __float2half_rn(wv - __half2float(hi));
    }
    g_bhi[idx] = hi;
    g_blo[idx] = lo;
}

// w_out [128][512] fp32 -> hi/lo fp16 (already [n][k] layout for mma)
__global__ void k_osplit(const float* __restrict__ w) {
    int idx = blockIdx.x*blockDim.x + threadIdx.x;
    if (idx >= NOUT*NHID) return;
    float wv = w[idx];
    __half hi = __float2half_rn(wv);
    g_ohi[idx] = hi;
    g_olo[idx] = __float2half_rn(wv - __half2float(hi));
}

// ================= GEMM1: mma.sync fp16 2-way split =================
// C[128x128 per CTA] = A[128xK] (spikes) x (Bhi + Blo)[128xK]^T, fp32 accum.
#define STAGE_BYTES 49152

__global__ void __launch_bounds__(256, 2) k_gemm1tc() {
    extern __shared__ char smem[];
    const int tid    = threadIdx.x;
    const int wid    = tid >> 5;
    const int lane   = tid & 31;
    const int warp_m = wid >> 1;
    const int warp_n = wid &  1;
    const int m_base = blockIdx.x * 128;
    const int n_base = blockIdx.y * 128;

    const uint32_t sbase = smem_u32(smem);

    auto load_tile = [&](int kc, int s) {
        const uint32_t st = sbase + s * STAGE_BYTES;
        const int kcol = kc * 64;
        #pragma unroll
        for (int it = 0; it < 4; it++) {
            int g = it * 256 + tid;
            int row = g >> 3, sub = g & 7;
            uint32_t off = row * 128 + sub * 16;
            const char* src = (const char*)(g_a16 + (size_t)(m_base + row)*KPAD + kcol) + sub*16;
            CP_ASYNC16(st + SWZ(off), src);
        }
        #pragma unroll
        for (int it = 0; it < 4; it++) {
            int g = it * 256 + tid;
            int row = g >> 3, sub = g & 7;
            uint32_t off = row * 128 + sub * 16;
            const char* srch = (const char*)(g_bhi + (size_t)(n_base + row)*KPAD + kcol) + sub*16;
            const char* srcl = (const char*)(g_blo + (size_t)(n_base + row)*KPAD + kcol) + sub*16;
            CP_ASYNC16(st + 16384 + SWZ(off), srch);
            CP_ASYNC16(st + 32768 + SWZ(off), srcl);
        }
        CP_COMMIT();
    };

    float acc[2][8][4];
    #pragma unroll
    for (int i = 0; i < 2; i++)
        #pragma unroll
        for (int j = 0; j < 8; j++)
            #pragma unroll
            for (int q = 0; q < 4; q++) acc[i][j][q] = 0.f;

    load_tile(0, 0);

    const int lrow = lane & 15, lcol = (lane >> 4) * 16;

    #pragma unroll 1
    for (int c = 0; c < NCH; c++) {
        const int buf = c & 1;
        if (c + 1 < NCH) { load_tile(c + 1, buf ^ 1); CP_WAIT(1); }
        else            { CP_WAIT(0); }
        __syncthreads();

        const uint32_t sA = sbase + buf * STAGE_BYTES;
        const uint32_t sBh = sA + 16384;
        const uint32_t sBl = sA + 32768;

        #pragma unroll
        for (int ks = 0; ks < 4; ks++) {
            uint32_t a[2][4], bh[4][4], bl[4][4];
            #pragma unroll
            for (int mt = 0; mt < 2; mt++) {
                uint32_t off = (uint32_t)(warp_m*32 + mt*16 + lrow)*128 + ks*32 + lcol;
                LDSM_X4(a[mt][0], a[mt][1], a[mt][2], a[mt][3], sA + SWZ(off));
            }
            #pragma unroll
            for (int nt = 0; nt < 4; nt++) {
                uint32_t off = (uint32_t)(warp_n*64 + nt*16 + lrow)*128 + ks*32 + lcol;
                uint32_t so = SWZ(off);
                LDSM_X4(bh[nt][0], bh[nt][1], bh[nt][2], bh[nt][3], sBh + so);
                LDSM_X4(bl[nt][0], bl[nt][1], bl[nt][2], bl[nt][3], sBl + so);
            }
            #pragma unroll
            for (int mt = 0; mt < 2; mt++)
                #pragma unroll
                for (int nt = 0; nt < 4; nt++) {
                    MMA16816(acc[mt][nt*2+0], a[mt][0],a[mt][1],a[mt][2],a[mt][3],
                             bh[nt][0], bh[nt][2]);
                    MMA16816(acc[mt][nt*2+1], a[mt][0],a[mt][1],a[mt][2],a[mt][3],
                             bh[nt][1], bh[nt][3]);
                    MMA16816(acc[mt][nt*2+0], a[mt][0],a[mt][1],a[mt][2],a[mt][3],
                             bl[nt][0], bl[nt][2]);
                    MMA16816(acc[mt][nt*2+1], a[mt][0],a[mt][1],a[mt][2],a[mt][3],
                             bl[nt][1], bl[nt][3]);
                }
        }
        __syncthreads();
    }

    const int erow = lane >> 2, ecol = (lane & 3) * 2;
    #pragma unroll
    for (int mt = 0; mt < 2; mt++) {
        #pragma unroll
        for (int nt = 0; nt < 8; nt++) {
            int col = n_base + warp_n*64 + nt*8 + ecol;
            int r0  = m_base + warp_m*32 + mt*16 + erow;
            float2 v0; v0.x = acc[mt][nt][0]; v0.y = acc[mt][nt][1];
            float2 v1; v1.x = acc[mt][nt][2]; v1.y = acc[mt][nt][3];
            *(float2*)(g_ch + (size_t)r0*NHID + col)       = v0;
            *(float2*)(g_ch + (size_t)(r0 + 8)*NHID + col) = v1;
        }
    }
}

// ================= LIF scan -> fp16 hidden spikes =================
__global__ void k_lif() {
    int gid = blockIdx.x*blockDim.x + threadIdx.x;   // b*512 + h
    float v = 0.0f, cur = 0.0f;
    float xs[8];
    #pragma unroll
    for (int p = 0; p < 8; p++) xs[p] = g_ch[(size_t)p*(BB*NHID) + gid];
    #pragma unroll 1
    for (int t0 = 0; t0 < TT; t0 += 8) {
        #pragma unroll
        for (int p = 0; p < 8; p++) {
            float x = xs[p];
            int tn = t0 + 8 + p;
            if (tn < TT) xs[p] = g_ch[(size_t)tn*(BB*NHID) + gid];
            v   = v + C_A*(cur - v);
            cur = cur*C_D + x;
            bool z = v > 1.0f;
            if (z) v = 0.0f;
            g_sh[(size_t)(t0 + p)*(BB*NHID) + gid] = __float2half_rn(z ? 1.0f : 0.0f);
        }
    }
}

// ================= GEMM2: mma.sync fp16 2-way split, K=512, N=128 =================
__global__ void __launch_bounds__(256, 2) k_gemm2tc() {
    extern __shared__ char smem[];
    const int tid    = threadIdx.x;
    const int wid    = tid >> 5;
    const int lane   = tid & 31;
    const int warp_m = wid >> 1;
    const int warp_n = wid &  1;
    const int m_base = blockIdx.x * 128;

    const uint32_t sbase = smem_u32(smem);

    auto load_tile = [&](int kc, int s) {
        const uint32_t st = sbase + s * STAGE_BYTES;
        const int kcol = kc * 64;
        #pragma unroll
        for (int it = 0; it < 4; it++) {
            int g = it * 256 + tid;
            int row = g >> 3, sub = g & 7;
            uint32_t off = row * 128 + sub * 16;
            const char* src = (const char*)(g_sh + (size_t)(m_base + row)*NHID + kcol) + sub*16;
            CP_ASYNC16(st + SWZ(off), src);
        }
        #pragma unroll
        for (int it = 0; it < 4; it++) {
            int g = it * 256 + tid;
            int row = g >> 3, sub = g & 7;
            uint32_t off = row * 128 + sub * 16;
            const char* srch = (const char*)(g_ohi + (size_t)row*NHID + kcol) + sub*16;
            const char* srcl = (const char*)(g_olo + (size_t)row*NHID + kcol) + sub*16;
            CP_ASYNC16(st + 16384 + SWZ(off), srch);
            CP_ASYNC16(st + 32768 + SWZ(off), srcl);
        }
        CP_COMMIT();
    };

    float acc[2][8][4];
    #pragma unroll
    for (int i = 0; i < 2; i++)
        #pragma unroll
        for (int j = 0; j < 8; j++)
            #pragma unroll
            for (int q = 0; q < 4; q++) acc[i][j][q] = 0.f;

    load_tile(0, 0);

    const int lrow = lane & 15, lcol = (lane >> 4) * 16;

    #pragma unroll 1
    for (int c = 0; c < NCH2; c++) {
        const int buf = c & 1;
        if (c + 1 < NCH2) { load_tile(c + 1, buf ^ 1); CP_WAIT(1); }
        else             { CP_WAIT(0); }
        __syncthreads();

        const uint32_t sA = sbase + buf * STAGE_BYTES;
        const uint32_t sBh = sA + 16384;
        const uint32_t sBl = sA + 32768;

        #pragma unroll
        for (int ks = 0; ks < 4; ks++) {
            uint32_t a[2][4], bh[4][4], bl[4][4];
            #pragma unroll
            for (int mt = 0; mt < 2; mt++) {
                uint32_t off = (uint32_t)(warp_m*32 + mt*16 + lrow)*128 + ks*32 + lcol;
                LDSM_X4(a[mt][0], a[mt][1], a[mt][2], a[mt][3], sA + SWZ(off));
            }
            #pragma unroll
            for (int nt = 0; nt < 4; nt++) {
                uint32_t off = (uint32_t)(warp_n*64 + nt*16 + lrow)*128 + ks*32 + lcol;
                uint32_t so = SWZ(off);
                LDSM_X4(bh[nt][0], bh[nt][1], bh[nt][2], bh[nt][3], sBh + so);
                LDSM_X4(bl[nt][0], bl[nt][1], bl[nt][2], bl[nt][3], sBl + so);
            }
            #pragma unroll
            for (int mt = 0; mt < 2; mt++)
                #pragma unroll
                for (int nt = 0; nt < 4; nt++) {
                    MMA16816(acc[mt][nt*2+0], a[mt][0],a[mt][1],a[mt][2],a[mt][3],
                             bh[nt][0], bh[nt][2]);
                    MMA16816(acc[mt][nt*2+1], a[mt][0],a[mt][1],a[mt][2],a[mt][3],
                             bh[nt][1], bh[nt][3]);
                    MMA16816(acc[mt][nt*2+0], a[mt][0],a[mt][1],a[mt][2],a[mt][3],
                             bl[nt][0], bl[nt][2]);
                    MMA16816(acc[mt][nt*2+1], a[mt][0],a[mt][1],a[mt][2],a[mt][3],
                             bl[nt][1], bl[nt][3]);
                }
        }
        __syncthreads();
    }

    const int erow = lane >> 2, ecol = (lane & 3) * 2;
    #pragma unroll
    for (int mt = 0; mt < 2; mt++) {
        #pragma unroll
        for (int nt = 0; nt < 8; nt++) {
            int col = warp_n*64 + nt*8 + ecol;
            int r0  = m_base + warp_m*32 + mt*16 + erow;
            float2 v0; v0.x = acc[mt][nt][0]; v0.y = acc[mt][nt][1];
            float2 v1; v1.x = acc[mt][nt][2]; v1.y = acc[mt][nt][3];
            *(float2*)(g_co + (size_t)r0*NOUT + col)       = v0;
            *(float2*)(g_co + (size_t)(r0 + 8)*NOUT + col) = v1;
        }
    }
}

// ================= LI scan with software prefetch =================
__global__ void k_li(float* __restrict__ out) {
    int gid = blockIdx.x*blockDim.x + threadIdx.x;
    float v = 0.0f, cur = 0.0f;
    float xs[8];
    #pragma unroll
    for (int p = 0; p < 8; p++) xs[p] = g_co[p*(BB*NOUT) + gid];
    #pragma unroll 1
    for (int t0 = 0; t0 < TT; t0 += 8) {
        #pragma unroll
        for (int p = 0; p < 8; p++) {
            float x = xs[p];
            int tn = t0 + 8 + p;
            if (tn < TT) xs[p] = g_co[tn*(BB*NOUT) + gid];
            v   = v + C_A*(cur - v);
            cur = cur*C_D + x;
            out[(t0 + p)*(BB*NOUT) + gid] = v;
        }
    }
}

// ================= launch =================
extern "C" void kernel_launch(void* const* d_in, const int* in_sizes, int n_in,
                              void* d_out, int out_size) {
    const float *spikes = nullptr, *wh = nullptr, *wo = nullptr;
    for (int i = 0; i < n_in; i++) {
        if      (in_sizes[i] == TT*BB*NIN) spikes = (const float*)d_in[i];
        else if (in_sizes[i] == NHID*NIN)  wh     = (const float*)d_in[i];
        else if (in_sizes[i] == NOUT*NHID) wo     = (const float*)d_in[i];
    }
    cudaFuncSetAttribute(k_gemm1tc, cudaFuncAttributeMaxDynamicSharedMemorySize,
                         2*STAGE_BYTES);
    cudaFuncSetAttribute(k_gemm2tc, cudaFuncAttributeMaxDynamicSharedMemorySize,
                         2*STAGE_BYTES);
    k_bsplit <<<(NHID*KPAD + 255)/256, 256>>>(wh);
    k_osplit <<<(NOUT*NHID + 255)/256, 256>>>(wo);
    k_a16    <<<MM, KPAD/2>>>(spikes);
    k_gemm1tc<<<dim3(MTILES, NHID/128), 256, 2*STAGE_BYTES>>>();
    k_lif    <<<(BB*NHID)/256, 256>>>();
    k_gemm2tc<<<MTILES, 256, 2*STAGE_BYTES>>>();
    k_li     <<<(BB*NOUT)/256, 256>>>((float*)d_out);
}

// round 7
// speedup vs baseline: 2.8204x; 1.0387x over previous
#include <cuda_runtime.h>
#include <cuda_fp16.h>
#include <stdint.h>

// Problem constants
#define TT   256
#define BB   128
#define NIN  784
#define NHID 512
#define NOUT 128
#define MM   (TT*BB)        // 32768 (t,b) pairs
#define KPAD 832            // 784 padded to 13*64
#define NCH  13             // gemm1 K chunks of 64
#define NCH2 8              // gemm2 K chunks of 64 (512/64)
#define MTILES (MM/128)     // 256

// CUBA constants (exactly fp32-rounded like JAX)
#define C_A ((float)(1e-6*(1.0/6e-6)))           // 0.16666667f
#define C_D ((float)(1.0 - 1e-6*(1.0/6e-6)))     // 0.8333333f

// ---- scratch (device globals; no allocations allowed) ----
__device__ __half   g_a16 [(size_t)MM*KPAD];   // spikes fp16 K-padded    54.5 MB
__device__ __half   g_bhi [NHID*KPAD];         // w_hidden hi fp16        0.85 MB
__device__ __half   g_blo [NHID*KPAD];         // w_hidden lo fp16        0.85 MB
__device__ __half   g_ohi [NOUT*NHID];         // w_out hi fp16           128 KB
__device__ __half   g_olo [NOUT*NHID];         // w_out lo fp16           128 KB
__device__ float    g_ch  [(size_t)MM*NHID];   // hidden synaptic input   67 MB
__device__ __half   g_sh  [(size_t)MM*NHID];   // hidden spikes fp16      33.5 MB
__device__ float    g_co  [MM*NOUT];           // output synaptic input   16.8 MB

// ================= PTX helpers =================
__device__ __forceinline__ uint32_t smem_u32(const void* p) {
    uint32_t a;
    asm("{ .reg .u64 t; cvta.to.shared.u64 t, %1; cvt.u32.u64 %0, t; }" : "=r"(a) : "l"(p));
    return a;
}
#define CP_ASYNC16(dst, src) \
    asm volatile("cp.async.cg.shared.global [%0], [%1], 16;" :: "r"(dst), "l"(src))
#define CP_COMMIT()  asm volatile("cp.async.commit_group;" ::: "memory")
#define CP_WAIT(n)   asm volatile("cp.async.wait_group %0;" :: "n"(n) : "memory")

#define LDSM_X4(r0,r1,r2,r3, a) \
    asm volatile("ldmatrix.sync.aligned.m8n8.x4.shared.b16 {%0,%1,%2,%3}, [%4];" \
        : "=r"(r0),"=r"(r1),"=r"(r2),"=r"(r3) : "r"(a))
#define MMA16816(d, a0,a1,a2,a3, b0,b1) \
    asm volatile("mma.sync.aligned.m16n8k16.row.col.f32.f16.f16.f32 " \
        "{%0,%1,%2,%3}, {%4,%5,%6,%7}, {%8,%9}, {%0,%1,%2,%3};" \
        : "+f"((d)[0]),"+f"((d)[1]),"+f"((d)[2]),"+f"((d)[3]) \
        : "r"(a0),"r"(a1),"r"(a2),"r"(a3),"r"(b0),"r"(b1))

#define SWZ(off) ((off) ^ (((off) >> 3) & 0x70))

// ================= conversion kernels =================
// spikes fp32 [MM][784] -> fp16 [MM][832] (pad zero); 4 cols/thread
__global__ void k_a16(const float* __restrict__ spikes) {
    int m = blockIdx.x;
    int c = threadIdx.x * 4;                 // 0..828
    __half2 h0, h1;
    if (c + 3 < NIN) {
        float4 v = *(const float4*)(spikes + (size_t)m*NIN + c);
        h0 = __floats2half2_rn(v.x, v.y);
        h1 = __floats2half2_rn(v.z, v.w);
    } else {
        float a0 = (c+0 < NIN) ? spikes[(size_t)m*NIN + c+0] : 0.f;
        float a1 = (c+1 < NIN) ? spikes[(size_t)m*NIN + c+1] : 0.f;
        float a2 = (c+2 < NIN) ? spikes[(size_t)m*NIN + c+2] : 0.f;
        float a3 = (c+3 < NIN) ? spikes[(size_t)m*NIN + c+3] : 0.f;
        h0 = __floats2half2_rn(a0, a1);
        h1 = __floats2half2_rn(a2, a3);
    }
    *(__half2*)(g_a16 + (size_t)m*KPAD + c)     = h0;
    *(__half2*)(g_a16 + (size_t)m*KPAD + c + 2) = h1;
}

// w_hidden [512][784] fp32 -> hi/lo fp16 [512][832]
__global__ void k_bsplit(const float* __restrict__ w) {
    int idx = blockIdx.x*blockDim.x + threadIdx.x;
    if (idx >= NHID*KPAD) return;
    int h = idx / KPAD, k = idx % KPAD;
    __half hi = __float2half_rn(0.f), lo = __float2half_rn(0.f);
    if (k < NIN) {
        float wv = w[h*NIN + k];
        hi = __float2half_rn(wv);
        lo = __float2half_rn(wv - __half2float(hi));
    }
    g_bhi[idx] = hi;
    g_blo[idx] = lo;
}

// w_out [128][512] fp32 -> hi/lo fp16 (already [n][k] layout for mma)
__global__ void k_osplit(const float* __restrict__ w) {
    int idx = blockIdx.x*blockDim.x + threadIdx.x;
    if (idx >= NOUT*NHID) return;
    float wv = w[idx];
    __half hi = __float2half_rn(wv);
    g_ohi[idx] = hi;
    g_olo[idx] = __float2half_rn(wv - __half2float(hi));
}

// ================= GEMM core (shared by gemm1/gemm2) =================
// Warp tile 64x32, warps 2(m) x 4(n). Single sync per chunk; hi-pass then lo-pass.
#define STAGE_BYTES 49152

template<int NCHUNKS, int AKSTRIDE, int NSTRIDE>
__device__ __forceinline__ void gemm_body(
    const __half* a_gmem, const __half* bhi_gmem, const __half* blo_gmem,
    float* c_gmem, int m_base, int n_base, char* smem)
{
    const int tid    = threadIdx.x;
    const int wid    = tid >> 5;
    const int lane   = tid & 31;
    const int warp_m = wid >> 2;            // 0..1  (64 rows)
    const int warp_n = wid &  3;            // 0..3  (32 cols)

    const uint32_t sbase = smem_u32(smem);

    auto load_tile = [&](int kc, int s) {
        const uint32_t st = sbase + s * STAGE_BYTES;
        const int kcol = kc * 64;
        #pragma unroll
        for (int it = 0; it < 4; it++) {
            int g = it * 256 + tid;
            int row = g >> 3, sub = g & 7;
            uint32_t off = row * 128 + sub * 16;
            const char* src = (const char*)(a_gmem + (size_t)(m_base + row)*AKSTRIDE + kcol) + sub*16;
            CP_ASYNC16(st + SWZ(off), src);
        }
        #pragma unroll
        for (int it = 0; it < 4; it++) {
            int g = it * 256 + tid;
            int row = g >> 3, sub = g & 7;
            uint32_t off = row * 128 + sub * 16;
            const char* srch = (const char*)(bhi_gmem + (size_t)(n_base + row)*AKSTRIDE + kcol) + sub*16;
            const char* srcl = (const char*)(blo_gmem + (size_t)(n_base + row)*AKSTRIDE + kcol) + sub*16;
            CP_ASYNC16(st + 16384 + SWZ(off), srch);
            CP_ASYNC16(st + 32768 + SWZ(off), srcl);
        }
        CP_COMMIT();
    };

    float acc[4][4][4];
    #pragma unroll
    for (int i = 0; i < 4; i++)
        #pragma unroll
        for (int j = 0; j < 4; j++)
            #pragma unroll
            for (int q = 0; q < 4; q++) acc[i][j][q] = 0.f;

    load_tile(0, 0);

    const int lrow = lane & 15, lcol = (lane >> 4) * 16;

    #pragma unroll 1
    for (int c = 0; c < NCHUNKS; c++) {
        const int buf = c & 1;
        CP_WAIT(0);
        __syncthreads();
        if (c + 1 < NCHUNKS) load_tile(c + 1, buf ^ 1);

        const uint32_t sA = sbase + buf * STAGE_BYTES;
        const uint32_t sBh = sA + 16384;
        const uint32_t sBl = sA + 32768;

        #pragma unroll
        for (int ks = 0; ks < 4; ks++) {
            uint32_t a[4][4], bh[2][4], bl[2][4];
            #pragma unroll
            for (int mt = 0; mt < 4; mt++) {
                uint32_t off = (uint32_t)(warp_m*64 + mt*16 + lrow)*128 + ks*32 + lcol;
                LDSM_X4(a[mt][0], a[mt][1], a[mt][2], a[mt][3], sA + SWZ(off));
            }
            #pragma unroll
            for (int nt = 0; nt < 2; nt++) {
                uint32_t off = (uint32_t)(warp_n*32 + nt*16 + lrow)*128 + ks*32 + lcol;
                uint32_t so = SWZ(off);
                LDSM_X4(bh[nt][0], bh[nt][1], bh[nt][2], bh[nt][3], sBh + so);
                LDSM_X4(bl[nt][0], bl[nt][1], bl[nt][2], bl[nt][3], sBl + so);
            }
            // hi pass (each acc touched once -> no back-to-back RAW)
            #pragma unroll
            for (int mt = 0; mt < 4; mt++)
                #pragma unroll
                for (int nt = 0; nt < 2; nt++) {
                    MMA16816(acc[mt][nt*2+0], a[mt][0],a[mt][1],a[mt][2],a[mt][3],
                             bh[nt][0], bh[nt][2]);
                    MMA16816(acc[mt][nt*2+1], a[mt][0],a[mt][1],a[mt][2],a[mt][3],
                             bh[nt][1], bh[nt][3]);
                }
            // lo pass
            #pragma unroll
            for (int mt = 0; mt < 4; mt++)
                #pragma unroll
                for (int nt = 0; nt < 2; nt++) {
                    MMA16816(acc[mt][nt*2+0], a[mt][0],a[mt][1],a[mt][2],a[mt][3],
                             bl[nt][0], bl[nt][2]);
                    MMA16816(acc[mt][nt*2+1], a[mt][0],a[mt][1],a[mt][2],a[mt][3],
                             bl[nt][1], bl[nt][3]);
                }
        }
    }

    const int erow = lane >> 2, ecol = (lane & 3) * 2;
    #pragma unroll
    for (int mt = 0; mt < 4; mt++) {
        #pragma unroll
        for (int j = 0; j < 4; j++) {
            int col = n_base + warp_n*32 + j*8 + ecol;
            int r0  = m_base + warp_m*64 + mt*16 + erow;
            float2 v0; v0.x = acc[mt][j][0]; v0.y = acc[mt][j][1];
            float2 v1; v1.x = acc[mt][j][2]; v1.y = acc[mt][j][3];
            *(float2*)(c_gmem + (size_t)r0*NSTRIDE + col)       = v0;
            *(float2*)(c_gmem + (size_t)(r0 + 8)*NSTRIDE + col) = v1;
        }
    }
}

__global__ void __launch_bounds__(256, 2) k_gemm1tc() {
    extern __shared__ char smem[];
    gemm_body<NCH, KPAD, NHID>(g_a16, g_bhi, g_blo, g_ch,
                               blockIdx.x * 128, blockIdx.y * 128, smem);
}

__global__ void __launch_bounds__(256, 2) k_gemm2tc() {
    extern __shared__ char smem[];
    gemm_body<NCH2, NHID, NOUT>(g_sh, g_ohi, g_olo, g_co,
                                blockIdx.x * 128, 0, smem);
}

// ================= LIF scan -> fp16 hidden spikes =================
__global__ void k_lif() {
    int gid = blockIdx.x*blockDim.x + threadIdx.x;   // b*512 + h
    float v = 0.0f, cur = 0.0f;
    float xs[8];
    #pragma unroll
    for (int p = 0; p < 8; p++) xs[p] = g_ch[(size_t)p*(BB*NHID) + gid];
    #pragma unroll 1
    for (int t0 = 0; t0 < TT; t0 += 8) {
        #pragma unroll
        for (int p = 0; p < 8; p++) {
            float x = xs[p];
            int tn = t0 + 8 + p;
            if (tn < TT) xs[p] = g_ch[(size_t)tn*(BB*NHID) + gid];
            v   = v + C_A*(cur - v);
            cur = cur*C_D + x;
            bool z = v > 1.0f;
            if (z) v = 0.0f;
            g_sh[(size_t)(t0 + p)*(BB*NHID) + gid] = __float2half_rn(z ? 1.0f : 0.0f);
        }
    }
}

// ================= LI scan with software prefetch =================
__global__ void k_li(float* __restrict__ out) {
    int gid = blockIdx.x*blockDim.x + threadIdx.x;
    float v = 0.0f, cur = 0.0f;
    float xs[8];
    #pragma unroll
    for (int p = 0; p < 8; p++) xs[p] = g_co[p*(BB*NOUT) + gid];
    #pragma unroll 1
    for (int t0 = 0; t0 < TT; t0 += 8) {
        #pragma unroll
        for (int p = 0; p < 8; p++) {
            float x = xs[p];
            int tn = t0 + 8 + p;
            if (tn < TT) xs[p] = g_co[tn*(BB*NOUT) + gid];
            v   = v + C_A*(cur - v);
            cur = cur*C_D + x;
            out[(t0 + p)*(BB*NOUT) + gid] = v;
        }
    }
}

// ================= launch =================
extern "C" void kernel_launch(void* const* d_in, const int* in_sizes, int n_in,
                              void* d_out, int out_size) {
    const float *spikes = nullptr, *wh = nullptr, *wo = nullptr;
    for (int i = 0; i < n_in; i++) {
        if      (in_sizes[i] == TT*BB*NIN) spikes = (const float*)d_in[i];
        else if (in_sizes[i] == NHID*NIN)  wh     = (const float*)d_in[i];
        else if (in_sizes[i] == NOUT*NHID) wo     = (const float*)d_in[i];
    }
    cudaFuncSetAttribute(k_gemm1tc, cudaFuncAttributeMaxDynamicSharedMemorySize,
                         2*STAGE_BYTES);
    cudaFuncSetAttribute(k_gemm2tc, cudaFuncAttributeMaxDynamicSharedMemorySize,
                         2*STAGE_BYTES);
    k_bsplit <<<(NHID*KPAD + 255)/256, 256>>>(wh);
    k_osplit <<<(NOUT*NHID + 255)/256, 256>>>(wo);
    k_a16    <<<MM, KPAD/4>>>(spikes);
    k_gemm1tc<<<dim3(MTILES, NHID/128), 256, 2*STAGE_BYTES>>>();
    k_lif    <<<(BB*NHID)/256, 256>>>();
    k_gemm2tc<<<MTILES, 256, 2*STAGE_BYTES>>>();
    k_li     <<<(BB*NOUT)/256, 256>>>((float*)d_out);
}